// round 8
// baseline (speedup 1.0000x reference)
#include <cuda_runtime.h>

// Global accumulators: [0]=pos_loss, [1]=neg_loss, [2]=pos_count, [3]=neg_count
__device__ double g_acc[4];

__global__ void init_kernel() {
    if (threadIdx.x < 4) g_acc[threadIdx.x] = 0.0;
}

// ---------------------------------------------------------------------------
// Positive branch: one warp per (level, batch, point). 3*2*128 = 768 points.
// ---------------------------------------------------------------------------
__global__ void pos_kernel(const float* __restrict__ lg0,
                           const float* __restrict__ lg1,
                           const float* __restrict__ lg2,
                           const int*   __restrict__ co0,
                           const int*   __restrict__ co1,
                           const int*   __restrict__ co2)
{
    const int warps_per_block = blockDim.x >> 5;
    const int wid  = (blockIdx.x * warps_per_block) + (threadIdx.x >> 5);
    const int lane = threadIdx.x & 31;
    if (wid >= 768) return;

    // decode level / batch / point
    int lvl, rem;
    if (wid < 256)      { lvl = 0; rem = wid; }
    else if (wid < 512) { lvl = 1; rem = wid - 256; }
    else                { lvl = 2; rem = wid - 512; }
    const int b = rem >> 7;        // 0..1
    const int p = rem & 127;       // 0..127

    const float* lg;
    const int*   co;
    int D;
    float factor;
    if (lvl == 0)      { lg = lg0; co = co0; D = 128; factor = 4.0f; }
    else if (lvl == 1) { lg = lg1; co = co1; D = 64;  factor = 2.0f; }
    else               { lg = lg2; co = co2; D = 32;  factor = 1.0f; }

    const int r = lvl + 1;
    const int n = 2 * r;            // window edge
    const int nwin = n * n * n;     // 8 / 64 / 216

    const int base = (b * 128 + p) * 4;
    const int a = co[base + 0];
    const int y = co[base + 1];
    const int x = co[base + 2];
    const int z = co[base + 3];

    const float valid = (a > -1) ? 1.0f : 0.0f;
    const int ac = min(max(a, 0), 1);
    const int yc = min(max(y, 0), D - 1);
    const int xc = min(max(x, 0), D - 1);
    const int zc = min(max(z, 0), D - 1);

    // plane base for (b, ac)
    const long long plane = ((long long)(b * 2 + ac)) * D * D * D;

    // window max (indices clipped to [0, D-1] on both sides, per reference)
    float wmax = -3.4e38f;
    for (int idx = lane; idx < nwin; idx += 32) {
        const int j = idx / (n * n);
        const int k = (idx / n) % n;
        const int l = idx % n;
        const int iy = min(max(yc - r + j, 0), D - 1);
        const int ix = min(max(xc - r + k, 0), D - 1);
        const int iz = min(max(zc - r + l, 0), D - 1);
        const float v = lg[plane + ((long long)iy * D + ix) * D + iz];
        wmax = fmaxf(wmax, v);
    }
    #pragma unroll
    for (int off = 16; off > 0; off >>= 1)
        wmax = fmaxf(wmax, __shfl_xor_sync(0xFFFFFFFFu, wmax, off));

    if (lane == 0) {
        const float point = lg[plane + ((long long)yc * D + xc) * D + zc];
        const bool near_low = (yc < r) || (xc < r) || (zc < r);
        const float lp = near_low ? point : wmax;

        // sigmoid / log_sigmoid, numerically stable
        float sig, logsig;
        if (lp >= 0.0f) {
            const float e = expf(-lp);
            sig    = 1.0f / (1.0f + e);
            logsig = -log1pf(e);          // log_sigmoid(lp)
        } else {
            const float e = expf(lp);
            sig    = e / (1.0f + e);
            logsig = lp - log1pf(e);
        }
        const float om = 1.0f - sig;
        const float w  = om * om * valid;         // (1-sigmoid)^ALPHA * valid
        const float loss = -logsig * w * factor;

        atomicAdd(&g_acc[0], (double)loss);
        atomicAdd(&g_acc[2], (double)w);
    }
}

// ---------------------------------------------------------------------------
// Negative branch: elementwise over all 3 levels, float4 vectorized,
// per-thread float partials -> block reduce -> double atomicAdd.
// ---------------------------------------------------------------------------
__global__ void __launch_bounds__(256)
neg_kernel(const float4* __restrict__ lg0, const float4* __restrict__ pr0, int n0v,
           const float4* __restrict__ lg1, const float4* __restrict__ pr1, int n1v,
           const float4* __restrict__ lg2, const float4* __restrict__ pr2, int n2v)
{
    const int total = n0v + n1v + n2v;
    float sL = 0.0f, sW = 0.0f;

    for (int i = blockIdx.x * blockDim.x + threadIdx.x; i < total;
         i += gridDim.x * blockDim.x) {
        const float4* L;
        const float4* P;
        int idx;
        float fac;
        if (i < n0v)              { L = lg0; P = pr0; idx = i;             fac = 4.0f; }
        else if (i < n0v + n1v)   { L = lg1; P = pr1; idx = i - n0v;       fac = 2.0f; }
        else                      { L = lg2; P = pr2; idx = i - n0v - n1v; fac = 1.0f; }

        const float4 x4 = L[idx];
        const float4 p4 = P[idx];
        const float xs[4] = {x4.x, x4.y, x4.z, x4.w};
        const float ps[4] = {p4.x, p4.y, p4.z, p4.w};

        #pragma unroll
        for (int c = 0; c < 4; ++c) {
            const float x = xs[c];
            const float mask = (ps[c] == -1.0f) ? 1.0f : 0.0f;
            // e = e^x ; sigmoid = e/(1+e) ; softplus = log(1+e)
            const float e   = __expf(x);
            const float t   = 1.0f + e;
            const float s   = __fdividef(e, t);
            const float nll = __logf(t);
            const float w   = s * s * mask;
            sL = fmaf(nll * fac, w, sL);
            sW += w;
        }
    }

    // block reduction
    #pragma unroll
    for (int off = 16; off > 0; off >>= 1) {
        sL += __shfl_xor_sync(0xFFFFFFFFu, sL, off);
        sW += __shfl_xor_sync(0xFFFFFFFFu, sW, off);
    }
    __shared__ float shL[8], shW[8];
    const int warp = threadIdx.x >> 5;
    const int lane = threadIdx.x & 31;
    if (lane == 0) { shL[warp] = sL; shW[warp] = sW; }
    __syncthreads();
    if (warp == 0) {
        float vL = (lane < (blockDim.x >> 5)) ? shL[lane] : 0.0f;
        float vW = (lane < (blockDim.x >> 5)) ? shW[lane] : 0.0f;
        #pragma unroll
        for (int off = 4; off > 0; off >>= 1) {
            vL += __shfl_xor_sync(0xFFFFFFFFu, vL, off);
            vW += __shfl_xor_sync(0xFFFFFFFFu, vW, off);
        }
        if (lane == 0) {
            atomicAdd(&g_acc[1], (double)vL);
            atomicAdd(&g_acc[3], (double)vW);
        }
    }
}

__global__ void finalize_kernel(float* __restrict__ out) {
    if (threadIdx.x < 4) out[threadIdx.x] = (float)g_acc[threadIdx.x];
}

extern "C" void kernel_launch(void* const* d_in, const int* in_sizes, int n_in,
                              void* d_out, int out_size)
{
    // -----------------------------------------------------------------------
    // Resolve inputs GENERICALLY from in_sizes (no hardcoded counts).
    // Expected buffers (any order):
    //   logits{i} & prob{i}: float, 2*2*D^3 elems, D in {128,64,32}
    //     -> the three DISTINCT large sizes, descending, are levels 0,1,2.
    //     -> within a level, logits{i} always appears BEFORE prob{i}
    //        (true for both dict-interleaved and signature-grouped order).
    //   coord{i}: int32, 2*128*4 = 1024 elems (small) -> level order by
    //        appearance.
    // -----------------------------------------------------------------------
    // Find the three distinct large sizes, sorted descending.
    int lvl_size[3] = {0, 0, 0};
    for (int i = 0; i < n_in; ++i) {
        const int sz = in_sizes[i];
        if (sz <= 4096) continue;  // coord buffers
        // insert into sorted-desc set of distinct sizes
        bool seen = false;
        for (int k = 0; k < 3; ++k) if (lvl_size[k] == sz) { seen = true; break; }
        if (seen) continue;
        for (int k = 0; k < 3; ++k) {
            if (sz > lvl_size[k]) {
                for (int m = 2; m > k; --m) lvl_size[m] = lvl_size[m - 1];
                lvl_size[k] = sz;
                break;
            }
        }
    }

    const float* lg[3] = {nullptr, nullptr, nullptr};
    const float* pr[3] = {nullptr, nullptr, nullptr};
    const int*   co[3] = {nullptr, nullptr, nullptr};
    int n_coord = 0;

    for (int i = 0; i < n_in; ++i) {
        const int sz = in_sizes[i];
        if (sz <= 4096) {
            if (n_coord < 3) co[n_coord++] = (const int*)d_in[i];
            continue;
        }
        int lvl = -1;
        for (int k = 0; k < 3; ++k) if (sz == lvl_size[k]) { lvl = k; break; }
        if (lvl < 0) continue;
        if (lg[lvl] == nullptr)      lg[lvl] = (const float*)d_in[i];
        else if (pr[lvl] == nullptr) pr[lvl] = (const float*)d_in[i];
    }

    // Defensive: if resolution failed, do nothing rather than crash.
    if (!lg[0] || !lg[1] || !lg[2] || !pr[0] || !pr[1] || !pr[2] ||
        !co[0] || !co[1] || !co[2]) {
        // Still must do *some* capturable work so the graph isn't empty.
        init_kernel<<<1, 32>>>();
        finalize_kernel<<<1, 32>>>((float*)d_out);
        return;
    }

    const int n0v = lvl_size[0] / 4;
    const int n1v = lvl_size[1] / 4;
    const int n2v = lvl_size[2] / 4;

    init_kernel<<<1, 32>>>();

    // pos: 768 warps, 4 warps/block -> 192 blocks
    pos_kernel<<<192, 128>>>(lg[0], lg[1], lg[2], co[0], co[1], co[2]);

    const int threads = 256;
    const int total_v = n0v + n1v + n2v;
    int blocks = (total_v + threads - 1) / threads;
    if (blocks > 2368) blocks = 2368;   // 148 SMs * 16
    neg_kernel<<<blocks, threads>>>((const float4*)lg[0], (const float4*)pr[0], n0v,
                                    (const float4*)lg[1], (const float4*)pr[1], n1v,
                                    (const float4*)lg[2], (const float4*)pr[2], n2v);

    finalize_kernel<<<1, 32>>>((float*)d_out);
}

// round 11
// speedup vs baseline: 1.1740x; 1.1740x over previous
#include <cuda_runtime.h>

// Global accumulators: [0]=pos_loss, [1]=neg_loss, [2]=pos_count, [3]=neg_count
// Zero-initialized at module load; the last finishing block resets them to
// zero after writing d_out, so every graph replay starts from the same state.
__device__ double g_acc[4];
__device__ unsigned int g_ticket;

// ---------------------------------------------------------------------------
// Fused kernel: pos branch (first 768 global warps, one point each) +
// neg branch (all threads, float4 grid-stride) + last-block finalize.
// ---------------------------------------------------------------------------
__global__ void __launch_bounds__(256)
fused_kernel(const float*  __restrict__ lgf0,
             const float*  __restrict__ lgf1,
             const float*  __restrict__ lgf2,
             const int*    __restrict__ co0,
             const int*    __restrict__ co1,
             const int*    __restrict__ co2,
             const float4* __restrict__ pr0,
             const float4* __restrict__ pr1,
             const float4* __restrict__ pr2,
             int n0v, int n1v, int n2v,
             float* __restrict__ out)
{
    const int warp = threadIdx.x >> 5;
    const int lane = threadIdx.x & 31;

    // =====================  POS branch (768 warps)  =====================
    const int gwarp = blockIdx.x * (blockDim.x >> 5) + warp;
    if (gwarp < 768) {
        int lvl, rem;
        if (gwarp < 256)      { lvl = 0; rem = gwarp; }
        else if (gwarp < 512) { lvl = 1; rem = gwarp - 256; }
        else                  { lvl = 2; rem = gwarp - 512; }
        const int b = rem >> 7;
        const int p = rem & 127;

        const float* lg;
        const int*   co;
        int D;
        float factor;
        if (lvl == 0)      { lg = lgf0; co = co0; D = 128; factor = 4.0f; }
        else if (lvl == 1) { lg = lgf1; co = co1; D = 64;  factor = 2.0f; }
        else               { lg = lgf2; co = co2; D = 32;  factor = 1.0f; }

        const int r = lvl + 1;
        const int n = 2 * r;
        const int nwin = n * n * n;        // 8 / 64 / 216

        const int base = (b * 128 + p) * 4;
        const int a = co[base + 0];
        const int y = co[base + 1];
        const int x = co[base + 2];
        const int z = co[base + 3];

        const float valid = (a > -1) ? 1.0f : 0.0f;
        const int ac = min(max(a, 0), 1);
        const int yc = min(max(y, 0), D - 1);
        const int xc = min(max(x, 0), D - 1);
        const int zc = min(max(z, 0), D - 1);

        const long long plane = ((long long)(b * 2 + ac)) * D * D * D;

        float wmax = -3.4e38f;
        for (int idx = lane; idx < nwin; idx += 32) {
            const int j = idx / (n * n);
            const int k = (idx / n) % n;
            const int l = idx % n;
            const int iy = min(max(yc - r + j, 0), D - 1);
            const int ix = min(max(xc - r + k, 0), D - 1);
            const int iz = min(max(zc - r + l, 0), D - 1);
            const float v = lg[plane + ((long long)iy * D + ix) * D + iz];
            wmax = fmaxf(wmax, v);
        }
        #pragma unroll
        for (int off = 16; off > 0; off >>= 1)
            wmax = fmaxf(wmax, __shfl_xor_sync(0xFFFFFFFFu, wmax, off));

        if (lane == 0) {
            const float point = lg[plane + ((long long)yc * D + xc) * D + zc];
            const bool near_low = (yc < r) || (xc < r) || (zc < r);
            const float lp = near_low ? point : wmax;

            float sig, logsig;
            if (lp >= 0.0f) {
                const float e = expf(-lp);
                sig    = 1.0f / (1.0f + e);
                logsig = -log1pf(e);
            } else {
                const float e = expf(lp);
                sig    = e / (1.0f + e);
                logsig = lp - log1pf(e);
            }
            const float om = 1.0f - sig;
            const float w  = om * om * valid;
            const float loss = -logsig * w * factor;

            atomicAdd(&g_acc[0], (double)loss);
            atomicAdd(&g_acc[2], (double)w);
        }
    }

    // =====================  NEG branch (all threads)  =====================
    const float4* lg0 = (const float4*)lgf0;
    const float4* lg1 = (const float4*)lgf1;
    const float4* lg2 = (const float4*)lgf2;

    const int total = n0v + n1v + n2v;
    float sL = 0.0f, sW = 0.0f;

    for (int i = blockIdx.x * blockDim.x + threadIdx.x; i < total;
         i += gridDim.x * blockDim.x) {
        const float4* L;
        const float4* P;
        int idx;
        float fac;
        if (i < n0v)            { L = lg0; P = pr0; idx = i;             fac = 4.0f; }
        else if (i < n0v + n1v) { L = lg1; P = pr1; idx = i - n0v;       fac = 2.0f; }
        else                    { L = lg2; P = pr2; idx = i - n0v - n1v; fac = 1.0f; }

        const float4 x4 = L[idx];
        const float4 p4 = P[idx];
        const float xs[4] = {x4.x, x4.y, x4.z, x4.w};
        const float ps[4] = {p4.x, p4.y, p4.z, p4.w};

        #pragma unroll
        for (int c = 0; c < 4; ++c) {
            const float x = xs[c];
            const float mask = (ps[c] == -1.0f) ? 1.0f : 0.0f;
            const float e   = __expf(x);
            const float t   = 1.0f + e;
            const float s   = __fdividef(e, t);
            const float nll = __logf(t);
            const float w   = s * s * mask;
            sL = fmaf(nll * fac, w, sL);
            sW += w;
        }
    }

    // block reduction of neg partials
    #pragma unroll
    for (int off = 16; off > 0; off >>= 1) {
        sL += __shfl_xor_sync(0xFFFFFFFFu, sL, off);
        sW += __shfl_xor_sync(0xFFFFFFFFu, sW, off);
    }
    __shared__ float shL[8], shW[8];
    if (lane == 0) { shL[warp] = sL; shW[warp] = sW; }
    __syncthreads();
    if (warp == 0) {
        float vL = (lane < 8) ? shL[lane] : 0.0f;
        float vW = (lane < 8) ? shW[lane] : 0.0f;
        #pragma unroll
        for (int off = 4; off > 0; off >>= 1) {
            vL += __shfl_xor_sync(0xFFFFFFFFu, vL, off);
            vW += __shfl_xor_sync(0xFFFFFFFFu, vW, off);
        }
        if (lane == 0) {
            atomicAdd(&g_acc[1], (double)vL);
            atomicAdd(&g_acc[3], (double)vW);
        }
    }
    __syncthreads();

    // =====================  last-block finalize  =====================
    if (threadIdx.x == 0) {
        __threadfence();
        const unsigned rank = atomicAdd(&g_ticket, 1u);
        if (rank == gridDim.x - 1) {
            __threadfence();
            // all blocks' atomics are visible now
            volatile double* acc = g_acc;
            out[0] = (float)acc[0];
            out[1] = (float)acc[1];
            out[2] = (float)acc[2];
            out[3] = (float)acc[3];
            // reset state for the next (graph-replayed) launch
            g_acc[0] = 0.0; g_acc[1] = 0.0; g_acc[2] = 0.0; g_acc[3] = 0.0;
            g_ticket = 0u;
        }
    }
}

extern "C" void kernel_launch(void* const* d_in, const int* in_sizes, int n_in,
                              void* d_out, int out_size)
{
    // Resolve inputs generically by element count (order-independent):
    // three distinct large float sizes (desc) = levels 0/1/2; within a level
    // logits appears before prob; small int buffers are coord0..2 in order.
    int lvl_size[3] = {0, 0, 0};
    for (int i = 0; i < n_in; ++i) {
        const int sz = in_sizes[i];
        if (sz <= 4096) continue;
        bool seen = false;
        for (int k = 0; k < 3; ++k) if (lvl_size[k] == sz) { seen = true; break; }
        if (seen) continue;
        for (int k = 0; k < 3; ++k) {
            if (sz > lvl_size[k]) {
                for (int m = 2; m > k; --m) lvl_size[m] = lvl_size[m - 1];
                lvl_size[k] = sz;
                break;
            }
        }
    }

    const float* lg[3] = {nullptr, nullptr, nullptr};
    const float* pr[3] = {nullptr, nullptr, nullptr};
    const int*   co[3] = {nullptr, nullptr, nullptr};
    int n_coord = 0;

    for (int i = 0; i < n_in; ++i) {
        const int sz = in_sizes[i];
        if (sz <= 4096) {
            if (n_coord < 3) co[n_coord++] = (const int*)d_in[i];
            continue;
        }
        int lvl = -1;
        for (int k = 0; k < 3; ++k) if (sz == lvl_size[k]) { lvl = k; break; }
        if (lvl < 0) continue;
        if (lg[lvl] == nullptr)      lg[lvl] = (const float*)d_in[i];
        else if (pr[lvl] == nullptr) pr[lvl] = (const float*)d_in[i];
    }

    if (!lg[0] || !lg[1] || !lg[2] || !pr[0] || !pr[1] || !pr[2] ||
        !co[0] || !co[1] || !co[2]) {
        return;  // should not happen for this problem
    }

    const int n0v = lvl_size[0] / 4;
    const int n1v = lvl_size[1] / 4;
    const int n2v = lvl_size[2] / 4;

    const int threads = 256;
    const int total_v = n0v + n1v + n2v;
    int blocks = (total_v + threads - 1) / threads;
    if (blocks > 2368) blocks = 2368;   // 148 SMs * 16
    if (blocks < 96)   blocks = 96;     // must cover 768 pos warps

    fused_kernel<<<blocks, threads>>>(lg[0], lg[1], lg[2],
                                      co[0], co[1], co[2],
                                      (const float4*)pr[0],
                                      (const float4*)pr[1],
                                      (const float4*)pr[2],
                                      n0v, n1v, n2v,
                                      (float*)d_out);
}

// round 12
// speedup vs baseline: 1.2991x; 1.1065x over previous
#include <cuda_runtime.h>

// Global accumulators: [0]=pos_loss, [1]=neg_loss, [2]=pos_count, [3]=neg_count
// Zero at module load; last finishing block resets them after writing d_out,
// so every graph replay starts from identical state.
__device__ double g_acc[4];
__device__ unsigned int g_ticket;

// Per-element focal-neg term; accumulates unscaled nll*w and w.
__device__ __forceinline__ void neg_elem(float x, float p, float& lL, float& lW)
{
    const float e   = __expf(x);
    const float t   = 1.0f + e;
    const float s   = __fdividef(e, t);      // sigmoid(x)
    const float nll = __logf(t);             // softplus(x) = -log_sigmoid(-x)
    const float w   = (p == -1.0f) ? s * s : 0.0f;
    lL = fmaf(nll, w, lL);
    lW += w;
}

__device__ __forceinline__ void neg_quad(const float4 x4, const float4 p4,
                                         float& lL, float& lW)
{
    neg_elem(x4.x, p4.x, lL, lW);
    neg_elem(x4.y, p4.y, lL, lW);
    neg_elem(x4.z, p4.z, lL, lW);
    neg_elem(x4.w, p4.w, lL, lW);
}

// One level: grid-stride, 2x unrolled (4 independent LDG.128 in flight).
__device__ __forceinline__ void neg_level(const float4* __restrict__ L,
                                          const float4* __restrict__ P,
                                          int nv, int gtid, int stride,
                                          float& lL, float& lW)
{
    int i = gtid;
    for (; i + stride < nv; i += 2 * stride) {
        const float4 a0 = L[i];
        const float4 p0 = P[i];
        const float4 a1 = L[i + stride];
        const float4 p1 = P[i + stride];
        neg_quad(a0, p0, lL, lW);
        neg_quad(a1, p1, lL, lW);
    }
    if (i < nv) {
        neg_quad(L[i], P[i], lL, lW);
    }
}

// ---------------------------------------------------------------------------
// Fused kernel: pos branch (first 768 global warps) + neg branch (per-level
// clean loops) + last-block finalize.
// ---------------------------------------------------------------------------
__global__ void __launch_bounds__(256)
fused_kernel(const float*  __restrict__ lgf0,
             const float*  __restrict__ lgf1,
             const float*  __restrict__ lgf2,
             const int*    __restrict__ co0,
             const int*    __restrict__ co1,
             const int*    __restrict__ co2,
             const float4* __restrict__ pr0,
             const float4* __restrict__ pr1,
             const float4* __restrict__ pr2,
             int n0v, int n1v, int n2v,
             float* __restrict__ out)
{
    const int warp = threadIdx.x >> 5;
    const int lane = threadIdx.x & 31;

    // =====================  POS branch (768 warps)  =====================
    const int gwarp = blockIdx.x * (blockDim.x >> 5) + warp;
    if (gwarp < 768) {
        int lvl, rem;
        if (gwarp < 256)      { lvl = 0; rem = gwarp; }
        else if (gwarp < 512) { lvl = 1; rem = gwarp - 256; }
        else                  { lvl = 2; rem = gwarp - 512; }
        const int b = rem >> 7;
        const int p = rem & 127;

        const float* lg;
        const int*   co;
        int D;
        float factor;
        if (lvl == 0)      { lg = lgf0; co = co0; D = 128; factor = 4.0f; }
        else if (lvl == 1) { lg = lgf1; co = co1; D = 64;  factor = 2.0f; }
        else               { lg = lgf2; co = co2; D = 32;  factor = 1.0f; }

        const int r = lvl + 1;
        const int n = 2 * r;
        const int nwin = n * n * n;        // 8 / 64 / 216

        const int base = (b * 128 + p) * 4;
        const int a = co[base + 0];
        const int y = co[base + 1];
        const int x = co[base + 2];
        const int z = co[base + 3];

        const float valid = (a > -1) ? 1.0f : 0.0f;
        const int ac = min(max(a, 0), 1);
        const int yc = min(max(y, 0), D - 1);
        const int xc = min(max(x, 0), D - 1);
        const int zc = min(max(z, 0), D - 1);

        const long long plane = ((long long)(b * 2 + ac)) * D * D * D;

        float wmax = -3.4e38f;
        for (int idx = lane; idx < nwin; idx += 32) {
            const int j = idx / (n * n);
            const int k = (idx / n) % n;
            const int l = idx % n;
            const int iy = min(max(yc - r + j, 0), D - 1);
            const int ix = min(max(xc - r + k, 0), D - 1);
            const int iz = min(max(zc - r + l, 0), D - 1);
            const float v = lg[plane + ((long long)iy * D + ix) * D + iz];
            wmax = fmaxf(wmax, v);
        }
        #pragma unroll
        for (int off = 16; off > 0; off >>= 1)
            wmax = fmaxf(wmax, __shfl_xor_sync(0xFFFFFFFFu, wmax, off));

        if (lane == 0) {
            const float point = lg[plane + ((long long)yc * D + xc) * D + zc];
            const bool near_low = (yc < r) || (xc < r) || (zc < r);
            const float lp = near_low ? point : wmax;

            float sig, logsig;
            if (lp >= 0.0f) {
                const float e = expf(-lp);
                sig    = 1.0f / (1.0f + e);
                logsig = -log1pf(e);
            } else {
                const float e = expf(lp);
                sig    = e / (1.0f + e);
                logsig = lp - log1pf(e);
            }
            const float om = 1.0f - sig;
            const float w  = om * om * valid;
            const float loss = -logsig * w * factor;

            atomicAdd(&g_acc[0], (double)loss);
            atomicAdd(&g_acc[2], (double)w);
        }
    }

    // =====================  NEG branch: per-level loops  =====================
    const int gtid   = blockIdx.x * blockDim.x + threadIdx.x;
    const int stride = gridDim.x * blockDim.x;

    float sL = 0.0f, sW = 0.0f;
    {
        float lL = 0.0f, lW = 0.0f;
        neg_level((const float4*)lgf0, pr0, n0v, gtid, stride, lL, lW);
        sL = fmaf(lL, 4.0f, sL);  sW += lW;
    }
    {
        float lL = 0.0f, lW = 0.0f;
        neg_level((const float4*)lgf1, pr1, n1v, gtid, stride, lL, lW);
        sL = fmaf(lL, 2.0f, sL);  sW += lW;
    }
    {
        float lL = 0.0f, lW = 0.0f;
        neg_level((const float4*)lgf2, pr2, n2v, gtid, stride, lL, lW);
        sL += lL;  sW += lW;
    }

    // block reduction of neg partials
    #pragma unroll
    for (int off = 16; off > 0; off >>= 1) {
        sL += __shfl_xor_sync(0xFFFFFFFFu, sL, off);
        sW += __shfl_xor_sync(0xFFFFFFFFu, sW, off);
    }
    __shared__ float shL[8], shW[8];
    if (lane == 0) { shL[warp] = sL; shW[warp] = sW; }
    __syncthreads();
    if (warp == 0) {
        float vL = (lane < 8) ? shL[lane] : 0.0f;
        float vW = (lane < 8) ? shW[lane] : 0.0f;
        #pragma unroll
        for (int off = 4; off > 0; off >>= 1) {
            vL += __shfl_xor_sync(0xFFFFFFFFu, vL, off);
            vW += __shfl_xor_sync(0xFFFFFFFFu, vW, off);
        }
        if (lane == 0) {
            atomicAdd(&g_acc[1], (double)vL);
            atomicAdd(&g_acc[3], (double)vW);
        }
    }
    __syncthreads();

    // =====================  last-block finalize  =====================
    if (threadIdx.x == 0) {
        __threadfence();
        const unsigned rank = atomicAdd(&g_ticket, 1u);
        if (rank == gridDim.x - 1) {
            __threadfence();
            volatile double* acc = g_acc;
            out[0] = (float)acc[0];
            out[1] = (float)acc[1];
            out[2] = (float)acc[2];
            out[3] = (float)acc[3];
            g_acc[0] = 0.0; g_acc[1] = 0.0; g_acc[2] = 0.0; g_acc[3] = 0.0;
            g_ticket = 0u;
        }
    }
}

extern "C" void kernel_launch(void* const* d_in, const int* in_sizes, int n_in,
                              void* d_out, int out_size)
{
    // Resolve inputs generically by element count (order-independent):
    // three distinct large float sizes (desc) = levels 0/1/2; within a level
    // logits appears before prob; small int buffers are coord0..2 in order.
    int lvl_size[3] = {0, 0, 0};
    for (int i = 0; i < n_in; ++i) {
        const int sz = in_sizes[i];
        if (sz <= 4096) continue;
        bool seen = false;
        for (int k = 0; k < 3; ++k) if (lvl_size[k] == sz) { seen = true; break; }
        if (seen) continue;
        for (int k = 0; k < 3; ++k) {
            if (sz > lvl_size[k]) {
                for (int m = 2; m > k; --m) lvl_size[m] = lvl_size[m - 1];
                lvl_size[k] = sz;
                break;
            }
        }
    }

    const float* lg[3] = {nullptr, nullptr, nullptr};
    const float* pr[3] = {nullptr, nullptr, nullptr};
    const int*   co[3] = {nullptr, nullptr, nullptr};
    int n_coord = 0;

    for (int i = 0; i < n_in; ++i) {
        const int sz = in_sizes[i];
        if (sz <= 4096) {
            if (n_coord < 3) co[n_coord++] = (const int*)d_in[i];
            continue;
        }
        int lvl = -1;
        for (int k = 0; k < 3; ++k) if (sz == lvl_size[k]) { lvl = k; break; }
        if (lvl < 0) continue;
        if (lg[lvl] == nullptr)      lg[lvl] = (const float*)d_in[i];
        else if (pr[lvl] == nullptr) pr[lvl] = (const float*)d_in[i];
    }

    if (!lg[0] || !lg[1] || !lg[2] || !pr[0] || !pr[1] || !pr[2] ||
        !co[0] || !co[1] || !co[2]) {
        return;  // should not happen for this problem
    }

    const int n0v = lvl_size[0] / 4;
    const int n1v = lvl_size[1] / 4;
    const int n2v = lvl_size[2] / 4;

    const int threads = 256;
    // One full wave: 148 SMs * 8 blocks (256 thr, <=32 regs -> 2048 thr/SM).
    const int blocks = 1184;

    fused_kernel<<<blocks, threads>>>(lg[0], lg[1], lg[2],
                                      co[0], co[1], co[2],
                                      (const float4*)pr[0],
                                      (const float4*)pr[1],
                                      (const float4*)pr[2],
                                      n0v, n1v, n2v,
                                      (float*)d_out);
}